// round 12
// baseline (speedup 1.0000x reference)
#include <cuda_runtime.h>
#include <cuda_bf16.h>

#define CONFIDENCE_F 0.95f
#define SMOOTHING_F  0.05f
#define C_DIM 2048                 // floats per row
#define F4_PER_ROW (C_DIM / 4)     // 512 float4
#define NBLOCKS 888                // 148 SMs x 6 CTAs, single wave
#define NBLOCKS_MAX 2048
#define L2E_F 1.4426950408889634f  // log2(e)
#define BIAS_F 12.0f               // exp bias: e^(x-12); x ~ N(0,1), safe for |x| < 100
#define NB_F (-BIAS_F * L2E_F)

// One (loss_sum, w_sum) partial per CTA + completion counter.
__device__ float2 g_cta[NBLOCKS_MAX];
__device__ unsigned int g_done = 0;    // reset by last CTA each run

// Warp-per-row, strided row assignment. 8 chunks of 2xfloat4 per thread,
// double-buffered, cross-row prefetch. No max pass: sum e^(x-12) via
// FFMA+EX2. Best-measured configuration (R8) + branch-free target index.
__global__ __launch_bounds__(256, 6)
void ls_row_kernel(const float4* __restrict__ x,
                   const int* __restrict__ t32,
                   const float* __restrict__ w,
                   float* __restrict__ out,
                   int B)
{
    __shared__ float2 s_red[8];
    __shared__ bool am_last;

    const int wid   = threadIdx.x >> 5;
    const int lane  = threadIdx.x & 31;
    const int gwarp = blockIdx.x * 8 + wid;
    const int nwarp = gridDim.x * 8;

    // Inline dtype detect: int64 targets < 2048 => odd words all zero.
    // 32 odd words checked => P(false int64 | int32 data) = 2048^-32 ~ 0.
    // Branch-free indexing: int64 low word (little-endian) IS the value,
    // so target[row] = t32[row << tshift].
    int oddw = t32[2 * lane + 1];
    const int tshift = (__ballot_sync(0xffffffff, oddw != 0) == 0u) ? 1 : 0;

    float loss_acc = 0.f, w_acc = 0.f;     // lane-0 accumulators (fixed order)

    float4 a[2], b[2];
    int row = gwarp;
    if (row < B) {                          // prologue: chunk 0 of first row
        const float4* xr0 = x + (size_t)row * F4_PER_ROW;
        a[0] = xr0[lane];
        a[1] = xr0[lane + 32];
    }

    for (; row < B; row += nwarp) {
        const float4* xr = x + (size_t)row * F4_PER_ROW;
        const int nrow = row + nwarp;

        // lane-0 side fetches at row start: latency hidden under row compute
        int ti = 0; float wt = 0.f, xt = 0.f;
        if (lane == 0) {
            ti = t32[row << tshift];
            ti = min(max(ti, 0), C_DIM - 1);
            wt = __ldg(&w[ti]);
            xt = ((const float*)xr)[ti];
        }

        float s0 = 0.f, s1 = 0.f, sx0 = 0.f, sx1 = 0.f;

        #pragma unroll
        for (int c = 0; c < 8; c++) {
            float4* cur = (c & 1) ? b : a;
            float4* nxt = (c & 1) ? a : b;
            if (c < 7) {                    // overlap: next chunk of this row
                nxt[0] = xr[lane + 64 * (c + 1)];
                nxt[1] = xr[lane + 64 * (c + 1) + 32];
            } else if (nrow < B) {          // overlap: chunk 0 of NEXT row
                const float4* xn = x + (size_t)nrow * F4_PER_ROW;
                nxt[0] = xn[lane];
                nxt[1] = xn[lane + 32];
            }
            // e^(x-12) = 2^(x*log2e - 12*log2e): FFMA + EX2 per element
            s0 += exp2f(fmaf(cur[0].x, L2E_F, NB_F))
                + exp2f(fmaf(cur[0].y, L2E_F, NB_F))
                + exp2f(fmaf(cur[0].z, L2E_F, NB_F))
                + exp2f(fmaf(cur[0].w, L2E_F, NB_F));
            s1 += exp2f(fmaf(cur[1].x, L2E_F, NB_F))
                + exp2f(fmaf(cur[1].y, L2E_F, NB_F))
                + exp2f(fmaf(cur[1].z, L2E_F, NB_F))
                + exp2f(fmaf(cur[1].w, L2E_F, NB_F));
            sx0 += (cur[0].x + cur[0].y) + (cur[0].z + cur[0].w);
            sx1 += (cur[1].x + cur[1].y) + (cur[1].z + cur[1].w);
        }

        float s  = s0 + s1;
        float sx = sx0 + sx1;

        #pragma unroll
        for (int o = 16; o; o >>= 1) {
            s  += __shfl_xor_sync(0xffffffff, s,  o);
            sx += __shfl_xor_sync(0xffffffff, sx, o);
        }

        if (lane == 0) {
            float lse    = BIAS_F + __logf(s);
            float nll    = lse - xt;                    // -logprob[target]
            float smooth = lse - sx * (1.0f / C_DIM);   // -mean(logprobs)
            loss_acc += CONFIDENCE_F * nll * wt + SMOOTHING_F * smooth;
            w_acc    += wt;
        }
    }

    // CTA reduction of 8 warp partials (fixed order -> deterministic)
    if (lane == 0) s_red[wid] = make_float2(loss_acc, w_acc);
    __syncthreads();
    if (threadIdx.x == 0) {
        float L = 0.f, W = 0.f;
        #pragma unroll
        for (int i = 0; i < 8; i++) { L += s_red[i].x; W += s_red[i].y; }
        g_cta[blockIdx.x] = make_float2(L, W);
        __threadfence();                   // publish partial before arriving
        unsigned int prev = atomicAdd(&g_done, 1u);
        am_last = (prev == gridDim.x - 1);
    }
    __syncthreads();
    if (!am_last) return;

    // ---- last CTA: reduce gridDim.x partials (L2-hot) ----
    __threadfence();                       // acquire all partials
    float ls = 0.f, ws = 0.f;
    for (int i = threadIdx.x; i < gridDim.x; i += blockDim.x) {
        float2 p = g_cta[i];
        ls += p.x; ws += p.y;
    }
    #pragma unroll
    for (int o = 16; o; o >>= 1) {
        ls += __shfl_xor_sync(0xffffffff, ls, o);
        ws += __shfl_xor_sync(0xffffffff, ws, o);
    }
    if (lane == 0) s_red[wid] = make_float2(ls, ws);
    __syncthreads();
    if (threadIdx.x == 0) {
        float L = 0.f, W = 0.f;
        #pragma unroll
        for (int i = 0; i < 8; i++) { L += s_red[i].x; W += s_red[i].y; }
        out[0] = L / W;
        g_done = 0;                        // deterministic graph replay
    }
}

extern "C" void kernel_launch(void* const* d_in, const int* in_sizes, int n_in,
                              void* d_out, int out_size)
{
    // Identify inputs by element count: x = largest, weight = smallest,
    // target = the remaining one.
    int ix = 0, it = 1, iw = 2;
    long long best = -1;
    for (int i = 0; i < n_in; i++)
        if ((long long)in_sizes[i] > best) { best = in_sizes[i]; ix = i; }
    long long small = best + 1;
    for (int i = 0; i < n_in; i++)
        if (i != ix && (long long)in_sizes[i] < small) { small = in_sizes[i]; iw = i; }
    for (int i = 0; i < n_in; i++)
        if (i != ix && i != iw) it = i;

    const float4* x   = (const float4*)d_in[ix];
    const int*    tgt = (const int*)d_in[it];
    const float*  w   = (const float*)d_in[iw];
    float* out = (float*)d_out;

    int B = in_sizes[ix] / C_DIM;

    int nblocks = NBLOCKS;                 // single persistent wave (6/SM)
    if (B < nblocks * 8) nblocks = (B + 7) / 8;
    if (nblocks < 1) nblocks = 1;
    if (nblocks > NBLOCKS_MAX) nblocks = NBLOCKS_MAX;

    ls_row_kernel<<<nblocks, 256>>>(x, tgt, w, out, B);
}

// round 13
// speedup vs baseline: 1.0447x; 1.0447x over previous
#include <cuda_runtime.h>
#include <cuda_bf16.h>

#define CONFIDENCE_F 0.95f
#define SMOOTHING_F  0.05f
#define C_DIM 2048                 // floats per row
#define F4_PER_ROW (C_DIM / 4)     // 512 float4
#define NBLOCKS_CAP 1036           // 148 SMs x 7 CTAs, single wave
#define NBLOCKS_MAX 2048
#define L2E_F 1.4426950408889634f  // log2(e)
#define BIAS_F 12.0f               // exp bias: e^(x-12); x ~ N(0,1), safe for |x| < 100
#define NB_F (-BIAS_F * L2E_F)

// One (loss_sum, w_sum) partial per CTA + completion counter.
__device__ float2 g_cta[NBLOCKS_MAX];
__device__ unsigned int g_done = 0;    // reset by last CTA each run

// Warp-per-row, strided rows, UNIFORM work (grid chosen so nwarp | B when
// possible: 8192 warps x exactly 4 rows for B=32768). 16 chunks of 1xfloat4
// per thread, double-buffered, cross-row prefetch. regs=32 -> 7 CTAs/SM.
__global__ __launch_bounds__(256, 7)
void ls_row_kernel(const float4* __restrict__ x,
                   const int* __restrict__ t32,
                   const float* __restrict__ w,
                   float* __restrict__ out,
                   int B)
{
    __shared__ float2 s_red[8];
    __shared__ bool am_last;

    const int wid   = threadIdx.x >> 5;
    const int lane  = threadIdx.x & 31;
    const int gwarp = blockIdx.x * 8 + wid;
    const int nwarp = gridDim.x * 8;

    // Inline dtype detect: int64 targets < 2048 => odd words all zero.
    // 32 odd words checked => P(false int64 | int32 data) = 2048^-32 ~ 0.
    int oddw = t32[2 * lane + 1];
    const bool is64 = (__ballot_sync(0xffffffff, oddw != 0) == 0u);

    float loss_acc = 0.f, w_acc = 0.f;     // lane-0 accumulators (fixed order)

    float4 buf[2];
    int row = gwarp;
    if (row < B) {                          // prologue: chunk 0 of first row
        const float4* xr0 = x + (size_t)row * F4_PER_ROW;
        buf[0] = xr0[lane];
    }

    for (; row < B; row += nwarp) {
        const float4* xr = x + (size_t)row * F4_PER_ROW;
        const int nrow = row + nwarp;
        const float4* xn = x + (size_t)nrow * F4_PER_ROW;  // used only if nrow < B

        // lane-0 side fetches at row start: latency hidden under row compute
        int ti = 0; float wt = 0.f, xt = 0.f;
        if (lane == 0) {
            ti = is64 ? (int)((const long long*)t32)[row] : t32[row];
            ti = min(max(ti, 0), C_DIM - 1);
            wt = __ldg(&w[ti]);
            xt = ((const float*)xr)[ti];
        }

        float s0 = 0.f, s1 = 0.f, sx0 = 0.f, sx1 = 0.f;

        #pragma unroll
        for (int c = 0; c < 16; c++) {
            float4 cur = buf[c & 1];
            // prefetch distance 1; 16 % 2 == 0 keeps buffer phase across rows
            if (c < 15)
                buf[(c + 1) & 1] = xr[lane + 32 * (c + 1)];
            else if (nrow < B)
                buf[(c + 1) & 1] = xn[lane];

            // e^(x-12) = 2^(x*log2e - 12*log2e): FFMA + EX2 per element
            s0 += exp2f(fmaf(cur.x, L2E_F, NB_F))
                + exp2f(fmaf(cur.y, L2E_F, NB_F));
            s1 += exp2f(fmaf(cur.z, L2E_F, NB_F))
                + exp2f(fmaf(cur.w, L2E_F, NB_F));
            sx0 += cur.x + cur.y;
            sx1 += cur.z + cur.w;
        }

        float s  = s0 + s1;
        float sx = sx0 + sx1;

        #pragma unroll
        for (int o = 16; o; o >>= 1) {
            s  += __shfl_xor_sync(0xffffffff, s,  o);
            sx += __shfl_xor_sync(0xffffffff, sx, o);
        }

        if (lane == 0) {
            float lse    = BIAS_F + __logf(s);
            float nll    = lse - xt;                    // -logprob[target]
            float smooth = lse - sx * (1.0f / C_DIM);   // -mean(logprobs)
            loss_acc += CONFIDENCE_F * nll * wt + SMOOTHING_F * smooth;
            w_acc    += wt;
        }
    }

    // CTA reduction of 8 warp partials (fixed order -> deterministic)
    if (lane == 0) s_red[wid] = make_float2(loss_acc, w_acc);
    __syncthreads();
    if (threadIdx.x == 0) {
        float L = 0.f, W = 0.f;
        #pragma unroll
        for (int i = 0; i < 8; i++) { L += s_red[i].x; W += s_red[i].y; }
        g_cta[blockIdx.x] = make_float2(L, W);
        __threadfence();                   // publish partial before arriving
        unsigned int prev = atomicAdd(&g_done, 1u);
        am_last = (prev == gridDim.x - 1);
    }
    __syncthreads();
    if (!am_last) return;

    // ---- last CTA: reduce gridDim.x partials (L2-hot) ----
    __threadfence();                       // acquire all partials
    float ls = 0.f, ws = 0.f;
    for (int i = threadIdx.x; i < gridDim.x; i += blockDim.x) {
        float2 p = g_cta[i];
        ls += p.x; ws += p.y;
    }
    #pragma unroll
    for (int o = 16; o; o >>= 1) {
        ls += __shfl_xor_sync(0xffffffff, ls, o);
        ws += __shfl_xor_sync(0xffffffff, ws, o);
    }
    if (lane == 0) s_red[wid] = make_float2(ls, ws);
    __syncthreads();
    if (threadIdx.x == 0) {
        float L = 0.f, W = 0.f;
        #pragma unroll
        for (int i = 0; i < 8; i++) { L += s_red[i].x; W += s_red[i].y; }
        out[0] = L / W;
        g_done = 0;                        // deterministic graph replay
    }
}

extern "C" void kernel_launch(void* const* d_in, const int* in_sizes, int n_in,
                              void* d_out, int out_size)
{
    // Identify inputs by element count: x = largest, weight = smallest,
    // target = the remaining one.
    int ix = 0, it = 1, iw = 2;
    long long best = -1;
    for (int i = 0; i < n_in; i++)
        if ((long long)in_sizes[i] > best) { best = in_sizes[i]; ix = i; }
    long long small = best + 1;
    for (int i = 0; i < n_in; i++)
        if (i != ix && (long long)in_sizes[i] < small) { small = in_sizes[i]; iw = i; }
    for (int i = 0; i < n_in; i++)
        if (i != ix && i != iw) it = i;

    const float4* x   = (const float4*)d_in[ix];
    const int*    tgt = (const int*)d_in[it];
    const float*  w   = (const float*)d_in[iw];
    float* out = (float*)d_out;

    int B = in_sizes[ix] / C_DIM;

    // Uniform work split: warps = B / rows_per_warp with rows_per_warp = 4
    // (B=32768 -> 8192 warps -> 1024 CTAs, exactly 4 rows each, one wave
    // at 7 CTAs/SM). Fallback: cap at single-wave capacity, strided loop
    // handles the remainder.
    int nblocks = (B + 31) / 32;           // 8 warps/CTA, 4 rows/warp
    if (nblocks > NBLOCKS_CAP) nblocks = NBLOCKS_CAP;
    if (nblocks < 1) nblocks = 1;
    if (nblocks > NBLOCKS_MAX) nblocks = NBLOCKS_MAX;

    ls_row_kernel<<<nblocks, 256>>>(x, tgt, w, out, B);
}

// round 14
// speedup vs baseline: 1.0520x; 1.0070x over previous
#include <cuda_runtime.h>
#include <cuda_bf16.h>

#define CONFIDENCE_F 0.95f
#define SMOOTHING_F  0.05f
#define C_DIM 2048                 // floats per row
#define F4_PER_ROW (C_DIM / 4)     // 512 float4
#define NBLOCKS 888                // 148 SMs x 6 CTAs, single wave
#define NBLOCKS_MAX 2048
#define L2E_F 1.4426950408889634f  // log2(e)
#define BIAS_F 12.0f               // exp bias: e^(x-12); x ~ N(0,1), safe for |x| < 100
#define NB_F (-BIAS_F * L2E_F)

// One (loss_sum, w_sum) partial per CTA + completion counter.
__device__ float2 g_cta[NBLOCKS_MAX];
__device__ unsigned int g_done = 0;    // reset by last CTA each run

// Warp-per-row. 8 chunks of 2xfloat4 per thread, double-buffered with
// cross-row prefetch. No max pass: sum e^(x-12) via FFMA+EX2.
// Best-measured configuration of the session (R8, 45.57 us).
__global__ __launch_bounds__(256, 6)
void ls_row_kernel(const float4* __restrict__ x,
                   const int* __restrict__ t32,
                   const float* __restrict__ w,
                   float* __restrict__ out,
                   int B)
{
    __shared__ float2 s_red[8];
    __shared__ bool am_last;

    const int wid   = threadIdx.x >> 5;
    const int lane  = threadIdx.x & 31;
    const int gwarp = blockIdx.x * 8 + wid;
    const int nwarp = gridDim.x * 8;

    // Inline dtype detect: int64 targets < 2048 => odd words all zero.
    // 32 odd words checked => P(false int64 | int32 data) = 2048^-32 ~ 0.
    int oddw = t32[2 * lane + 1];
    const bool is64 = (__ballot_sync(0xffffffff, oddw != 0) == 0u);

    float loss_acc = 0.f, w_acc = 0.f;     // lane-0 accumulators (fixed order)

    float4 a[2], b[2];
    int row = gwarp;
    if (row < B) {                          // prologue: chunk 0 of first row
        const float4* xr = x + (size_t)row * F4_PER_ROW;
        a[0] = xr[lane];
        a[1] = xr[lane + 32];
    }

    for (; row < B; row += nwarp) {
        const float4* xr = x + (size_t)row * F4_PER_ROW;
        const int nrow = row + nwarp;

        // lane-0 side fetches at row start: latency hidden under row compute
        int ti = 0; float wt = 0.f, xt = 0.f;
        if (lane == 0) {
            ti = is64 ? (int)((const long long*)t32)[row] : t32[row];
            ti = min(max(ti, 0), C_DIM - 1);
            wt = __ldg(&w[ti]);
            xt = ((const float*)xr)[ti];
        }

        float s0 = 0.f, s1 = 0.f, sx0 = 0.f, sx1 = 0.f;

        #pragma unroll
        for (int c = 0; c < 8; c++) {
            float4* cur = (c & 1) ? b : a;
            float4* nxt = (c & 1) ? a : b;
            if (c < 7) {                    // overlap: next chunk of this row
                nxt[0] = xr[lane + 64 * (c + 1)];
                nxt[1] = xr[lane + 64 * (c + 1) + 32];
            } else if (nrow < B) {          // overlap: chunk 0 of NEXT row
                const float4* xn = x + (size_t)nrow * F4_PER_ROW;
                nxt[0] = xn[lane];
                nxt[1] = xn[lane + 32];
            }
            // e^(x-12) = 2^(x*log2e - 12*log2e): FFMA + EX2 per element
            s0 += exp2f(fmaf(cur[0].x, L2E_F, NB_F))
                + exp2f(fmaf(cur[0].y, L2E_F, NB_F))
                + exp2f(fmaf(cur[0].z, L2E_F, NB_F))
                + exp2f(fmaf(cur[0].w, L2E_F, NB_F));
            s1 += exp2f(fmaf(cur[1].x, L2E_F, NB_F))
                + exp2f(fmaf(cur[1].y, L2E_F, NB_F))
                + exp2f(fmaf(cur[1].z, L2E_F, NB_F))
                + exp2f(fmaf(cur[1].w, L2E_F, NB_F));
            sx0 += (cur[0].x + cur[0].y) + (cur[0].z + cur[0].w);
            sx1 += (cur[1].x + cur[1].y) + (cur[1].z + cur[1].w);
        }

        float s  = s0 + s1;
        float sx = sx0 + sx1;

        #pragma unroll
        for (int o = 16; o; o >>= 1) {
            s  += __shfl_xor_sync(0xffffffff, s,  o);
            sx += __shfl_xor_sync(0xffffffff, sx, o);
        }

        if (lane == 0) {
            float lse    = BIAS_F + __logf(s);
            float nll    = lse - xt;                    // -logprob[target]
            float smooth = lse - sx * (1.0f / C_DIM);   // -mean(logprobs)
            loss_acc += CONFIDENCE_F * nll * wt + SMOOTHING_F * smooth;
            w_acc    += wt;
        }
    }

    // CTA reduction of 8 warp partials (fixed order -> deterministic)
    if (lane == 0) s_red[wid] = make_float2(loss_acc, w_acc);
    __syncthreads();
    if (threadIdx.x == 0) {
        float L = 0.f, W = 0.f;
        #pragma unroll
        for (int i = 0; i < 8; i++) { L += s_red[i].x; W += s_red[i].y; }
        g_cta[blockIdx.x] = make_float2(L, W);
        __threadfence();                   // publish partial before arriving
        unsigned int prev = atomicAdd(&g_done, 1u);
        am_last = (prev == gridDim.x - 1);
    }
    __syncthreads();
    if (!am_last) return;

    // ---- last CTA: reduce gridDim.x partials (L2-hot) ----
    __threadfence();                       // acquire all partials
    float ls = 0.f, ws = 0.f;
    for (int i = threadIdx.x; i < gridDim.x; i += blockDim.x) {
        float2 p = g_cta[i];
        ls += p.x; ws += p.y;
    }
    #pragma unroll
    for (int o = 16; o; o >>= 1) {
        ls += __shfl_xor_sync(0xffffffff, ls, o);
        ws += __shfl_xor_sync(0xffffffff, ws, o);
    }
    if (lane == 0) s_red[wid] = make_float2(ls, ws);
    __syncthreads();
    if (threadIdx.x == 0) {
        float L = 0.f, W = 0.f;
        #pragma unroll
        for (int i = 0; i < 8; i++) { L += s_red[i].x; W += s_red[i].y; }
        out[0] = L / W;
        g_done = 0;                        // deterministic graph replay
    }
}

extern "C" void kernel_launch(void* const* d_in, const int* in_sizes, int n_in,
                              void* d_out, int out_size)
{
    // Identify inputs by element count: x = largest, weight = smallest,
    // target = the remaining one.
    int ix = 0, it = 1, iw = 2;
    long long best = -1;
    for (int i = 0; i < n_in; i++)
        if ((long long)in_sizes[i] > best) { best = in_sizes[i]; ix = i; }
    long long small = best + 1;
    for (int i = 0; i < n_in; i++)
        if (i != ix && (long long)in_sizes[i] < small) { small = in_sizes[i]; iw = i; }
    for (int i = 0; i < n_in; i++)
        if (i != ix && i != iw) it = i;

    const float4* x   = (const float4*)d_in[ix];
    const int*    tgt = (const int*)d_in[it];
    const float*  w   = (const float*)d_in[iw];
    float* out = (float*)d_out;

    int B = in_sizes[ix] / C_DIM;

    int nblocks = NBLOCKS;                 // single persistent wave (6/SM)
    if (B < nblocks * 8) nblocks = (B + 7) / 8;
    if (nblocks < 1) nblocks = 1;
    if (nblocks > NBLOCKS_MAX) nblocks = NBLOCKS_MAX;

    ls_row_kernel<<<nblocks, 256>>>(x, tgt, w, out, B);
}